// round 6
// baseline (speedup 1.0000x reference)
#include <cuda_runtime.h>
#include <math.h>
#include <stdint.h>

#define BB 4
#define CC 64
#define OO 64
#define HH 128
#define WW 128
#define HW (HH*WW)
#define KT 9

// ---- smem layout (float offsets) ----
#define S_AFH   0        // A hi fragments [8t][8q][32 lane][4]   (8192)
#define S_AFL   8192     // A lo fragments                        (8192)
#define S_OFFJ  16384    // [18][128]                             (2304)
#define S_CW    18688    // float4[128]                           (512)
#define S_CI    19200    // int4[128]                             (512)
#define S_OFFW  19712    // [64][20]                              (1280)
#define S_SC    20992    // [18]
#define S_SB    21010    // [18]
#define S_BIAS  21028    // [64]
#define SMEM_FLOATS 21092
#define SMEM_BYTES (SMEM_FLOATS*4)

// B fragments: [k][q][nt][lane][4] = (b0_hi, b1_hi, b0_lo, b1_lo)
__device__ float g_bf[KT*8*8*32*4];

__device__ __forceinline__ float tf32r(float a) {
    uint32_t u;
    asm("cvt.rna.tf32.f32 %0, %1;" : "=r"(u) : "f"(a));
    return __uint_as_float(u);
}

__global__ void prep_bf_kernel(const float* __restrict__ w) {
    int i = blockIdx.x * 256 + threadIdx.x;         // over KT*8*8*32 = 18432
    if (i >= KT*8*8*32) return;
    int lane = i & 31;
    int nt   = (i >> 5) & 7;
    int q    = (i >> 8) & 7;
    int k    = i >> 11;
    int cc  = lane & 3;
    int gid = lane >> 2;
    int o   = nt*8 + gid;
    int c0  = q*8 + cc;
    int c1  = c0 + 4;
    float w0 = w[(o*CC + c0)*KT + k];
    float w1 = w[(o*CC + c1)*KT + k];
    float h0 = tf32r(w0), h1 = tf32r(w1);
    float4 v = make_float4(h0, h1, w0 - h0, w1 - h1);
    ((float4*)g_bf)[i] = v;
}

__device__ __forceinline__ void mma_tf32(float* d, const uint32_t* a, uint32_t b0, uint32_t b1) {
    asm volatile(
        "mma.sync.aligned.m16n8k8.row.col.f32.tf32.tf32.f32 "
        "{%0,%1,%2,%3}, {%4,%5,%6,%7}, {%8,%9}, {%0,%1,%2,%3};"
        : "+f"(d[0]), "+f"(d[1]), "+f"(d[2]), "+f"(d[3])
        : "r"(a[0]), "r"(a[1]), "r"(a[2]), "r"(a[3]), "r"(b0), "r"(b1));
}

__global__ __launch_bounds__(256, 2) void deform_main_kernel(
    const float* __restrict__ x,
    const float* __restrict__ off_w,
    const float* __restrict__ off_b,
    const float* __restrict__ bn_gamma,
    const float* __restrict__ bn_beta,
    const float* __restrict__ bn_mean,
    const float* __restrict__ bn_var,
    const float* __restrict__ dconv_b,
    float* __restrict__ out)
{
    extern __shared__ float smem[];

    const int tid  = threadIdx.x;
    const int lane = tid & 31;
    const int wid  = tid >> 5;          // 8 warps
    const int b    = blockIdx.x >> 7;
    const int h    = blockIdx.x & 127;
    const float* xb = x + (size_t)b * CC * HW;

    // ---- Prologue ----
    for (int i = tid; i < 18*CC; i += 256) {
        int j = i / CC, c = i % CC;
        smem[S_OFFW + c*20 + j] = off_w[i];
    }
    if (tid < 18) {
        float sc = bn_gamma[tid] * rsqrtf(bn_var[tid] + 1e-5f);
        smem[S_SC + tid] = sc;
        smem[S_SB + tid] = (off_b[tid] - bn_mean[tid]) * sc + bn_beta[tid];
    }
    if (tid >= 64 && tid < 128) smem[S_BIAS + tid - 64] = dconv_b[tid - 64];
    __syncthreads();

    // ---- Offset branch: 2 threads per pixel, 9 j's each ----
    {
        const int pix = tid & 127;
        const int jb  = (tid >> 7) * 9;
        const int p   = h*WW + pix;
        float a9[9];
        #pragma unroll
        for (int j = 0; j < 9; j++) a9[j] = 0.f;
        #pragma unroll 4
        for (int c = 0; c < CC; c++) {
            float xv = __ldg(xb + c*HW + p);
            const float* r = smem + S_OFFW + c*20 + jb;
            #pragma unroll
            for (int j = 0; j < 9; j++) a9[j] += xv * r[j];
        }
        #pragma unroll
        for (int jj = 0; jj < 9; jj++) {
            int j = jb + jj;
            float v = a9[jj] * smem[S_SC + j] + smem[S_SB + j];
            smem[S_OFFJ + j*128 + pix] = tanhf(v) * 0.75f;
        }
    }

    // warp roles for MMA: pg = pixel group (32 pix), og = output group (32 o)
    const int pg = wid >> 1;
    const int og = wid & 1;
    // gather role: q = wid, channels c0 = 8q + (lane&3), c1 = c0+4
    const int g_c0 = 8*wid + (lane & 3);
    const int g_r  = lane >> 2;

    float acc[2][4][4];
    #pragma unroll
    for (int t = 0; t < 2; t++)
        #pragma unroll
        for (int n = 0; n < 4; n++)
            #pragma unroll
            for (int e = 0; e < 4; e++) acc[t][n][e] = 0.f;

    const float4* s_cw4 = (const float4*)(smem + S_CW);
    const int4*   s_ci4 = (const int4*)(smem + S_CI);

    #pragma unroll 1
    for (int k = 0; k < KT; k++) {
        // ---- corners for tap k (threads 0..127); also separates MMA(k-1) from gather(k)
        __syncthreads();
        if (tid < 128) {
            const int pix = tid;
            const int kyi = k / 3 - 1;
            const int kxi = k % 3 - 1;
            float py = (float)(h + kyi)   + smem[S_OFFJ + (2*k)*128 + pix];
            float px = (float)(pix + kxi) + smem[S_OFFJ + (2*k+1)*128 + pix];
            float fy = floorf(py), fx = floorf(px);
            float wy = py - fy,    wx = px - fx;
            int y0 = (int)fy, x0 = (int)fx;
            int y1 = y0 + 1,  x1 = x0 + 1;
            float vy0 = (y0 >= 0 && y0 < HH) ? 1.f : 0.f;
            float vy1 = (y1 >= 0 && y1 < HH) ? 1.f : 0.f;
            float vx0 = (x0 >= 0 && x0 < WW) ? 1.f : 0.f;
            float vx1 = (x1 >= 0 && x1 < WW) ? 1.f : 0.f;
            float4 wv;
            wv.x = (1.f - wy) * (1.f - wx) * vy0 * vx0;
            wv.y = (1.f - wy) * wx         * vy0 * vx1;
            wv.z = wy         * (1.f - wx) * vy1 * vx0;
            wv.w = wy         * wx         * vy1 * vx1;
            int yc0 = min(max(y0, 0), HH-1), yc1 = min(max(y1, 0), HH-1);
            int xc0 = min(max(x0, 0), WW-1), xc1 = min(max(x1, 0), WW-1);
            int4 iv;
            iv.x = yc0*WW + xc0; iv.y = yc0*WW + xc1;
            iv.z = yc1*WW + xc0; iv.w = yc1*WW + xc1;
            ((float4*)(smem + S_CW))[pix] = wv;
            ((int4*)(smem + S_CI))[pix]   = iv;
        }
        __syncthreads();

        // ---- gather: 8 tasks/thread, thread owns fragment slot (t=i, q=wid, lane)
        const float* bp0 = xb + (size_t)g_c0 * HW;
        const float* bp1 = bp0 + 4*HW;
        #pragma unroll
        for (int i = 0; i < 8; i++) {
            int p0 = 16*i + g_r;
            int p1 = p0 + 8;
            float4 w0 = s_cw4[p0]; int4 i0 = s_ci4[p0];
            float4 w1 = s_cw4[p1]; int4 i1 = s_ci4[p1];
            // a0=(p0,c0) a1=(p1,c0) a2=(p0,c1) a3=(p1,c1)
            float s0 = w0.x*__ldg(bp0+i0.x) + w0.y*__ldg(bp0+i0.y)
                     + w0.z*__ldg(bp0+i0.z) + w0.w*__ldg(bp0+i0.w);
            float s1 = w1.x*__ldg(bp0+i1.x) + w1.y*__ldg(bp0+i1.y)
                     + w1.z*__ldg(bp0+i1.z) + w1.w*__ldg(bp0+i1.w);
            float s2 = w0.x*__ldg(bp1+i0.x) + w0.y*__ldg(bp1+i0.y)
                     + w0.z*__ldg(bp1+i0.z) + w0.w*__ldg(bp1+i0.w);
            float s3 = w1.x*__ldg(bp1+i1.x) + w1.y*__ldg(bp1+i1.y)
                     + w1.z*__ldg(bp1+i1.z) + w1.w*__ldg(bp1+i1.w);
            float h0 = tf32r(s0), h1 = tf32r(s1), h2 = tf32r(s2), h3 = tf32r(s3);
            int slot = ((i*8 + wid)*32 + lane)*4;
            ((float4*)(smem + S_AFH))[slot>>2] = make_float4(h0, h1, h2, h3);
            ((float4*)(smem + S_AFL))[slot>>2] = make_float4(s0-h0, s1-h1, s2-h2, s3-h3);
        }
        __syncthreads();

        // ---- MMA: warp tile 32 pix x 32 o, 3-pass tf32 split, B via LDG.128 ----
        {
            const uint4* bsrc = (const uint4*)g_bf;
            // fragment group index: ((k*8 + q)*8 + nt), lane entry = *32 + lane
            uint4 bcur[4], bnxt[4];
            #pragma unroll
            for (int j = 0; j < 4; j++)
                bcur[j] = __ldg(bsrc + ((k*8 + 0)*8 + og*4 + j)*32 + lane);

            #pragma unroll
            for (int q = 0; q < 8; q++) {
                if (q < 7) {
                    #pragma unroll
                    for (int j = 0; j < 4; j++)
                        bnxt[j] = __ldg(bsrc + ((k*8 + q+1)*8 + og*4 + j)*32 + lane);
                }
                const int t0 = 2*pg, t1 = 2*pg + 1;
                float4 fh0 = ((const float4*)(smem + S_AFH))[((t0*8+q)*32 + lane)];
                float4 fl0 = ((const float4*)(smem + S_AFL))[((t0*8+q)*32 + lane)];
                float4 fh1 = ((const float4*)(smem + S_AFH))[((t1*8+q)*32 + lane)];
                float4 fl1 = ((const float4*)(smem + S_AFL))[((t1*8+q)*32 + lane)];
                uint32_t ah0[4] = {__float_as_uint(fh0.x), __float_as_uint(fh0.y),
                                   __float_as_uint(fh0.z), __float_as_uint(fh0.w)};
                uint32_t al0[4] = {__float_as_uint(fl0.x), __float_as_uint(fl0.y),
                                   __float_as_uint(fl0.z), __float_as_uint(fl0.w)};
                uint32_t ah1[4] = {__float_as_uint(fh1.x), __float_as_uint(fh1.y),
                                   __float_as_uint(fh1.z), __float_as_uint(fh1.w)};
                uint32_t al1[4] = {__float_as_uint(fl1.x), __float_as_uint(fl1.y),
                                   __float_as_uint(fl1.z), __float_as_uint(fl1.w)};
                #pragma unroll
                for (int j = 0; j < 4; j++) {
                    uint32_t bh0 = bcur[j].x, bh1 = bcur[j].y;
                    uint32_t bl0 = bcur[j].z, bl1 = bcur[j].w;
                    mma_tf32(acc[0][j], ah0, bh0, bh1);
                    mma_tf32(acc[0][j], al0, bh0, bh1);
                    mma_tf32(acc[0][j], ah0, bl0, bl1);
                    mma_tf32(acc[1][j], ah1, bh0, bh1);
                    mma_tf32(acc[1][j], al1, bh0, bh1);
                    mma_tf32(acc[1][j], ah1, bl0, bl1);
                }
                #pragma unroll
                for (int j = 0; j < 4; j++) bcur[j] = bnxt[j];
            }
        }
    }

    // ---- Epilogue: fragment regs -> out, add bias ----
    // c0: D[pix][o], c1: D[pix][o+1], c2: D[pix+8][o], c3: D[pix+8][o+1]
    const int pix0 = pg*32 + (lane >> 2);
    const int o00  = og*32 + 2*(lane & 3);
    float* ob = out + (size_t)b*OO*HW + h*WW;
    #pragma unroll
    for (int t = 0; t < 2; t++) {
        int p = pix0 + 16*t;
        #pragma unroll
        for (int j = 0; j < 4; j++) {
            int o = o00 + 8*j;
            float b0 = smem[S_BIAS + o];
            float b1 = smem[S_BIAS + o + 1];
            ob[(size_t)o*HW + p]         = acc[t][j][0] + b0;
            ob[(size_t)(o+1)*HW + p]     = acc[t][j][1] + b1;
            ob[(size_t)o*HW + p + 8]     = acc[t][j][2] + b0;
            ob[(size_t)(o+1)*HW + p + 8] = acc[t][j][3] + b1;
        }
    }
}

extern "C" void kernel_launch(void* const* d_in, const int* in_sizes, int n_in,
                              void* d_out, int out_size) {
    const float* x        = (const float*)d_in[0];
    const float* off_w    = (const float*)d_in[1];
    const float* off_b    = (const float*)d_in[2];
    const float* bn_gamma = (const float*)d_in[3];
    const float* bn_beta  = (const float*)d_in[4];
    const float* bn_mean  = (const float*)d_in[5];
    const float* bn_var   = (const float*)d_in[6];
    const float* dconv_w  = (const float*)d_in[7];
    const float* dconv_b  = (const float*)d_in[8];
    float* out = (float*)d_out;

    cudaFuncSetAttribute(deform_main_kernel,
                         cudaFuncAttributeMaxDynamicSharedMemorySize, SMEM_BYTES);

    prep_bf_kernel<<<(KT*8*8*32 + 255)/256, 256>>>(dconv_w);
    deform_main_kernel<<<BB*HH, 256, SMEM_BYTES>>>(
        x, off_w, off_b, bn_gamma, bn_beta, bn_mean, bn_var, dconv_b, out);
}

// round 7
// speedup vs baseline: 1.7732x; 1.7732x over previous
#include <cuda_runtime.h>
#include <math.h>
#include <stdint.h>

#define BB 4
#define CC 64
#define OO 64
#define HH 128
#define WW 128
#define HW (HH*WW)
#define KT 9
#define ST 68    // samp row stride (floats): 68 mod 32 == 4 -> conflict-free

// ---- smem layout (float offsets) ----
#define S_AH    0                 // samp_hi [128][68]  (8704)
#define S_AL    8704              // samp_lo [128][68]  (8704)
#define S_OFFJ  17408             // [18][128]          (2304)
#define S_OFFW  19712             // [64][20]           (1280)
#define S_SC    20992             // [18]
#define S_SB    21010             // [18]
#define S_BIAS  21028             // [64]
#define SMEM_FLOATS 21092
#define SMEM_BYTES (SMEM_FLOATS*4)

// B fragments: [k][q][nt][lane][4] = (b0_hi, b1_hi, b0_lo, b1_lo)
__device__ float g_bf[KT*8*8*32*4];

__device__ __forceinline__ float tf32r(float a) {
    uint32_t u;
    asm("cvt.rna.tf32.f32 %0, %1;" : "=r"(u) : "f"(a));
    return __uint_as_float(u);
}

__global__ void prep_bf_kernel(const float* __restrict__ w) {
    int i = blockIdx.x * 256 + threadIdx.x;         // over KT*8*8*32 = 18432
    if (i >= KT*8*8*32) return;
    int lane = i & 31;
    int nt   = (i >> 5) & 7;
    int q    = (i >> 8) & 7;
    int k    = i >> 11;
    int cc  = lane & 3;
    int gid = lane >> 2;
    int o   = nt*8 + gid;
    int c0  = q*8 + cc;
    int c1  = c0 + 4;
    float w0 = w[(o*CC + c0)*KT + k];
    float w1 = w[(o*CC + c1)*KT + k];
    float h0 = tf32r(w0), h1 = tf32r(w1);
    float4 v = make_float4(h0, h1, w0 - h0, w1 - h1);
    ((float4*)g_bf)[i] = v;
}

__device__ __forceinline__ void mma_tf32(float* d, const uint32_t* a, uint32_t b0, uint32_t b1) {
    asm volatile(
        "mma.sync.aligned.m16n8k8.row.col.f32.tf32.tf32.f32 "
        "{%0,%1,%2,%3}, {%4,%5,%6,%7}, {%8,%9}, {%0,%1,%2,%3};"
        : "+f"(d[0]), "+f"(d[1]), "+f"(d[2]), "+f"(d[3])
        : "r"(a[0]), "r"(a[1]), "r"(a[2]), "r"(a[3]), "r"(b0), "r"(b1));
}

__global__ __launch_bounds__(256, 2) void deform_main_kernel(
    const float* __restrict__ x,
    const float* __restrict__ off_w,
    const float* __restrict__ off_b,
    const float* __restrict__ bn_gamma,
    const float* __restrict__ bn_beta,
    const float* __restrict__ bn_mean,
    const float* __restrict__ bn_var,
    const float* __restrict__ dconv_b,
    float* __restrict__ out)
{
    extern __shared__ float smem[];

    const int tid  = threadIdx.x;
    const int lane = tid & 31;
    const int wid  = tid >> 5;          // 8 warps
    const int b    = blockIdx.x >> 7;
    const int h    = blockIdx.x & 127;
    const int pix  = tid & 127;         // gather pixel (warp = 32 consecutive)
    const int half = tid >> 7;          // gathers channels [32*half, 32*half+32)
    const float* xb = x + (size_t)b * CC * HW;

    // ---- Prologue ----
    for (int i = tid; i < 18*CC; i += 256) {
        int j = i / CC, c = i % CC;
        smem[S_OFFW + c*20 + j] = off_w[i];
    }
    if (tid < 18) {
        float sc = bn_gamma[tid] * rsqrtf(bn_var[tid] + 1e-5f);
        smem[S_SC + tid] = sc;
        smem[S_SB + tid] = (off_b[tid] - bn_mean[tid]) * sc + bn_beta[tid];
    }
    if (tid >= 64 && tid < 128) smem[S_BIAS + tid - 64] = dconv_b[tid - 64];
    __syncthreads();

    // ---- Offset branch: 2 threads per pixel, 9 j's each ----
    {
        const int jb = half * 9;
        const int p  = h*WW + pix;
        float a9[9];
        #pragma unroll
        for (int j = 0; j < 9; j++) a9[j] = 0.f;
        #pragma unroll 4
        for (int c = 0; c < CC; c++) {
            float xv = __ldg(xb + c*HW + p);
            const float* r = smem + S_OFFW + c*20 + jb;
            #pragma unroll
            for (int j = 0; j < 9; j++) a9[j] += xv * r[j];
        }
        #pragma unroll
        for (int jj = 0; jj < 9; jj++) {
            int j = jb + jj;
            float v = a9[jj] * smem[S_SC + j] + smem[S_SB + j];
            smem[S_OFFJ + j*128 + pix] = tanhf(v) * 0.75f;
        }
    }

    // MMA warp roles: pg = pixel group (32 pix), og = output group (32 o)
    const int pg = wid >> 1;
    const int og = wid & 1;

    float acc[2][4][4];
    #pragma unroll
    for (int t = 0; t < 2; t++)
        #pragma unroll
        for (int n = 0; n < 4; n++)
            #pragma unroll
            for (int e = 0; e < 4; e++) acc[t][n][e] = 0.f;

    #pragma unroll 1
    for (int k = 0; k < KT; k++) {
        __syncthreads();   // MMA(k-1) done reading samp

        // ---- corners inline (per thread; both halves redundantly) ----
        float4 wv; int4 iv;
        {
            const int kyi = k / 3 - 1;
            const int kxi = k % 3 - 1;
            float py = (float)(h + kyi)   + smem[S_OFFJ + (2*k)*128 + pix];
            float px = (float)(pix + kxi) + smem[S_OFFJ + (2*k+1)*128 + pix];
            float fy = floorf(py), fx = floorf(px);
            float wy = py - fy,    wx = px - fx;
            int y0 = (int)fy, x0 = (int)fx;
            int y1 = y0 + 1,  x1 = x0 + 1;
            float vy0 = (y0 >= 0 && y0 < HH) ? 1.f : 0.f;
            float vy1 = (y1 >= 0 && y1 < HH) ? 1.f : 0.f;
            float vx0 = (x0 >= 0 && x0 < WW) ? 1.f : 0.f;
            float vx1 = (x1 >= 0 && x1 < WW) ? 1.f : 0.f;
            wv.x = (1.f - wy) * (1.f - wx) * vy0 * vx0;
            wv.y = (1.f - wy) * wx         * vy0 * vx1;
            wv.z = wy         * (1.f - wx) * vy1 * vx0;
            wv.w = wy         * wx         * vy1 * vx1;
            int yc0 = min(max(y0, 0), HH-1), yc1 = min(max(y1, 0), HH-1);
            int xc0 = min(max(x0, 0), WW-1), xc1 = min(max(x1, 0), WW-1);
            iv.x = yc0*WW + xc0; iv.y = yc0*WW + xc1;
            iv.z = yc1*WW + xc0; iv.w = yc1*WW + xc1;
        }

        // ---- gather: 32 channels per thread, coalesced LDG, STS.128 x2 per 4c ----
        {
            const int cb = half * 32;
            float* ah = smem + S_AH + pix*ST + cb;
            float* al = smem + S_AL + pix*ST + cb;
            #pragma unroll
            for (int g = 0; g < 8; g++) {
                float h4[4], l4[4];
                #pragma unroll
                for (int e = 0; e < 4; e++) {
                    const float* bp = xb + (size_t)(cb + g*4 + e)*HW;
                    float s = wv.x*__ldg(bp + iv.x) + wv.y*__ldg(bp + iv.y)
                            + wv.z*__ldg(bp + iv.z) + wv.w*__ldg(bp + iv.w);
                    h4[e] = tf32r(s);
                    l4[e] = s - h4[e];
                }
                *(float4*)(ah + g*4) = make_float4(h4[0], h4[1], h4[2], h4[3]);
                *(float4*)(al + g*4) = make_float4(l4[0], l4[1], l4[2], l4[3]);
            }
        }
        __syncthreads();   // samp ready

        // ---- MMA: warp tile 32 pix x 32 o, 3-pass tf32 split ----
        {
            const uint4* bsrc = (const uint4*)g_bf;
            uint4 bcur[4], bnxt[4];
            #pragma unroll
            for (int j = 0; j < 4; j++)
                bcur[j] = __ldg(bsrc + ((k*8 + 0)*8 + og*4 + j)*32 + lane);

            const int prow = pg*32 + (lane >> 2);
            #pragma unroll
            for (int q = 0; q < 8; q++) {
                if (q < 7) {
                    #pragma unroll
                    for (int j = 0; j < 4; j++)
                        bnxt[j] = __ldg(bsrc + ((k*8 + q+1)*8 + og*4 + j)*32 + lane);
                }
                const int ccol = q*8 + (lane & 3);
                uint32_t ah[2][4], al[2][4];
                #pragma unroll
                for (int tt = 0; tt < 2; tt++) {
                    const float* ph = smem + S_AH + (prow + 16*tt)*ST + ccol;
                    const float* pl = smem + S_AL + (prow + 16*tt)*ST + ccol;
                    ah[tt][0] = __float_as_uint(ph[0]);
                    ah[tt][1] = __float_as_uint(ph[8*ST]);
                    ah[tt][2] = __float_as_uint(ph[4]);
                    ah[tt][3] = __float_as_uint(ph[8*ST + 4]);
                    al[tt][0] = __float_as_uint(pl[0]);
                    al[tt][1] = __float_as_uint(pl[8*ST]);
                    al[tt][2] = __float_as_uint(pl[4]);
                    al[tt][3] = __float_as_uint(pl[8*ST + 4]);
                }
                #pragma unroll
                for (int j = 0; j < 4; j++) {
                    uint32_t bh0 = bcur[j].x, bh1 = bcur[j].y;
                    uint32_t bl0 = bcur[j].z, bl1 = bcur[j].w;
                    mma_tf32(acc[0][j], ah[0], bh0, bh1);
                    mma_tf32(acc[0][j], al[0], bh0, bh1);
                    mma_tf32(acc[0][j], ah[0], bl0, bl1);
                    mma_tf32(acc[1][j], ah[1], bh0, bh1);
                    mma_tf32(acc[1][j], al[1], bh0, bh1);
                    mma_tf32(acc[1][j], ah[1], bl0, bl1);
                }
                #pragma unroll
                for (int j = 0; j < 4; j++) bcur[j] = bnxt[j];
            }
        }
    }

    // ---- Epilogue: fragment regs -> out, add bias ----
    const int pix0 = pg*32 + (lane >> 2);
    const int o00  = og*32 + 2*(lane & 3);
    float* ob = out + (size_t)b*OO*HW + h*WW;
    #pragma unroll
    for (int t = 0; t < 2; t++) {
        int p = pix0 + 16*t;
        #pragma unroll
        for (int j = 0; j < 4; j++) {
            int o = o00 + 8*j;
            float b0 = smem[S_BIAS + o];
            float b1 = smem[S_BIAS + o + 1];
            ob[(size_t)o*HW + p]         = acc[t][j][0] + b0;
            ob[(size_t)(o+1)*HW + p]     = acc[t][j][1] + b1;
            ob[(size_t)o*HW + p + 8]     = acc[t][j][2] + b0;
            ob[(size_t)(o+1)*HW + p + 8] = acc[t][j][3] + b1;
        }
    }
}

extern "C" void kernel_launch(void* const* d_in, const int* in_sizes, int n_in,
                              void* d_out, int out_size) {
    const float* x        = (const float*)d_in[0];
    const float* off_w    = (const float*)d_in[1];
    const float* off_b    = (const float*)d_in[2];
    const float* bn_gamma = (const float*)d_in[3];
    const float* bn_beta  = (const float*)d_in[4];
    const float* bn_mean  = (const float*)d_in[5];
    const float* bn_var   = (const float*)d_in[6];
    const float* dconv_w  = (const float*)d_in[7];
    const float* dconv_b  = (const float*)d_in[8];
    float* out = (float*)d_out;

    cudaFuncSetAttribute(deform_main_kernel,
                         cudaFuncAttributeMaxDynamicSharedMemorySize, SMEM_BYTES);

    prep_bf_kernel<<<(KT*8*8*32 + 255)/256, 256>>>(dconv_w);
    deform_main_kernel<<<BB*HH, 256, SMEM_BYTES>>>(
        x, off_w, off_b, bn_gamma, bn_beta, bn_mean, bn_var, dconv_b, out);
}

// round 8
// speedup vs baseline: 2.1278x; 1.1999x over previous
#include <cuda_runtime.h>
#include <math.h>
#include <stdint.h>

#define BB 4
#define CC 64
#define OO 64
#define HH 128
#define WW 128
#define HW (HH*WW)
#define KT 9
#define ST 68    // samp row stride (floats): 68 mod 32 == 4 -> conflict-free

// ---- smem layout (float offsets) ----
#define S_SAMP  0                 // samp fp32 [128][68]  (8704)
#define S_OFFJ  8704              // [18][128]            (2304)
#define S_OFFW  11008             // [64][20]             (1280)
#define S_SC    12288             // [18]
#define S_SB    12306             // [18]
#define S_BIAS  12324             // [64]
#define SMEM_FLOATS 12388
#define SMEM_BYTES (SMEM_FLOATS*4)

// B fragments (hi only): [k][q][nt][lane][2] = (b0_hi, b1_hi)
__device__ float g_bf[KT*8*8*32*2];

__device__ __forceinline__ float tf32r(float a) {
    uint32_t u;
    asm("cvt.rna.tf32.f32 %0, %1;" : "=r"(u) : "f"(a));
    return __uint_as_float(u);
}

__global__ void prep_bf_kernel(const float* __restrict__ w) {
    int i = blockIdx.x * 256 + threadIdx.x;         // over KT*8*8*32 = 18432
    if (i >= KT*8*8*32) return;
    int lane = i & 31;
    int nt   = (i >> 5) & 7;
    int q    = (i >> 8) & 7;
    int k    = i >> 11;
    int cc  = lane & 3;
    int gid = lane >> 2;
    int o   = nt*8 + gid;
    int c0  = q*8 + cc;
    int c1  = c0 + 4;
    float w0 = w[(o*CC + c0)*KT + k];
    float w1 = w[(o*CC + c1)*KT + k];
    ((float2*)g_bf)[i] = make_float2(tf32r(w0), tf32r(w1));
}

__device__ __forceinline__ void mma_tf32(float* d, const uint32_t* a, uint32_t b0, uint32_t b1) {
    asm volatile(
        "mma.sync.aligned.m16n8k8.row.col.f32.tf32.tf32.f32 "
        "{%0,%1,%2,%3}, {%4,%5,%6,%7}, {%8,%9}, {%0,%1,%2,%3};"
        : "+f"(d[0]), "+f"(d[1]), "+f"(d[2]), "+f"(d[3])
        : "r"(a[0]), "r"(a[1]), "r"(a[2]), "r"(a[3]), "r"(b0), "r"(b1));
}

__global__ __launch_bounds__(256, 2) void deform_main_kernel(
    const float* __restrict__ x,
    const float* __restrict__ off_w,
    const float* __restrict__ off_b,
    const float* __restrict__ bn_gamma,
    const float* __restrict__ bn_beta,
    const float* __restrict__ bn_mean,
    const float* __restrict__ bn_var,
    const float* __restrict__ dconv_b,
    float* __restrict__ out)
{
    extern __shared__ float smem[];

    const int tid  = threadIdx.x;
    const int lane = tid & 31;
    const int wid  = tid >> 5;          // 8 warps
    const int b    = blockIdx.x >> 7;
    const int h    = blockIdx.x & 127;
    const int pix  = tid & 127;         // gather pixel (warp = 32 consecutive)
    const int half = tid >> 7;          // gathers channels [32*half, 32*half+32)
    const float* xb = x + (size_t)b * CC * HW;

    // ---- Prologue ----
    for (int i = tid; i < 18*CC; i += 256) {
        int j = i / CC, c = i % CC;
        smem[S_OFFW + c*20 + j] = off_w[i];
    }
    if (tid < 18) {
        float sc = bn_gamma[tid] * rsqrtf(bn_var[tid] + 1e-5f);
        smem[S_SC + tid] = sc;
        smem[S_SB + tid] = (off_b[tid] - bn_mean[tid]) * sc + bn_beta[tid];
    }
    if (tid >= 64 && tid < 128) smem[S_BIAS + tid - 64] = dconv_b[tid - 64];
    __syncthreads();

    // ---- Offset branch: 2 threads per pixel, 9 j's each ----
    {
        const int jb = half * 9;
        const int p  = h*WW + pix;
        float a9[9];
        #pragma unroll
        for (int j = 0; j < 9; j++) a9[j] = 0.f;
        #pragma unroll 4
        for (int c = 0; c < CC; c++) {
            float xv = __ldg(xb + c*HW + p);
            const float* r = smem + S_OFFW + c*20 + jb;
            #pragma unroll
            for (int j = 0; j < 9; j++) a9[j] += xv * r[j];
        }
        #pragma unroll
        for (int jj = 0; jj < 9; jj++) {
            int j = jb + jj;
            float v = a9[jj] * smem[S_SC + j] + smem[S_SB + j];
            smem[S_OFFJ + j*128 + pix] = tanhf(v) * 0.75f;
        }
    }

    // MMA warp roles: pg = pixel group (32 pix), og = output group (32 o)
    const int pg = wid >> 1;
    const int og = wid & 1;

    float acc[2][4][4];
    #pragma unroll
    for (int t = 0; t < 2; t++)
        #pragma unroll
        for (int n = 0; n < 4; n++)
            #pragma unroll
            for (int e = 0; e < 4; e++) acc[t][n][e] = 0.f;

    #pragma unroll 1
    for (int k = 0; k < KT; k++) {
        __syncthreads();   // MMA(k-1) done reading samp

        // ---- corners inline (per thread) ----
        float4 wv; int4 iv;
        {
            const int kyi = k / 3 - 1;
            const int kxi = k % 3 - 1;
            float py = (float)(h + kyi)   + smem[S_OFFJ + (2*k)*128 + pix];
            float px = (float)(pix + kxi) + smem[S_OFFJ + (2*k+1)*128 + pix];
            float fy = floorf(py), fx = floorf(px);
            float wy = py - fy,    wx = px - fx;
            int y0 = (int)fy, x0 = (int)fx;
            int y1 = y0 + 1,  x1 = x0 + 1;
            float vy0 = (y0 >= 0 && y0 < HH) ? 1.f : 0.f;
            float vy1 = (y1 >= 0 && y1 < HH) ? 1.f : 0.f;
            float vx0 = (x0 >= 0 && x0 < WW) ? 1.f : 0.f;
            float vx1 = (x1 >= 0 && x1 < WW) ? 1.f : 0.f;
            wv.x = (1.f - wy) * (1.f - wx) * vy0 * vx0;
            wv.y = (1.f - wy) * wx         * vy0 * vx1;
            wv.z = wy         * (1.f - wx) * vy1 * vx0;
            wv.w = wy         * wx         * vy1 * vx1;
            int yc0 = min(max(y0, 0), HH-1), yc1 = min(max(y1, 0), HH-1);
            int xc0 = min(max(x0, 0), WW-1), xc1 = min(max(x1, 0), WW-1);
            iv.x = yc0*WW + xc0; iv.y = yc0*WW + xc1;
            iv.z = yc1*WW + xc0; iv.w = yc1*WW + xc1;
        }

        // ---- gather: 32 channels per thread, coalesced LDG, 1 STS.128 per 4c ----
        {
            const int cb = half * 32;
            float* as = smem + S_SAMP + pix*ST + cb;
            #pragma unroll
            for (int g = 0; g < 8; g++) {
                float s4[4];
                #pragma unroll
                for (int e = 0; e < 4; e++) {
                    const float* bp = xb + (size_t)(cb + g*4 + e)*HW;
                    s4[e] = wv.x*__ldg(bp + iv.x) + wv.y*__ldg(bp + iv.y)
                          + wv.z*__ldg(bp + iv.z) + wv.w*__ldg(bp + iv.w);
                }
                *(float4*)(as + g*4) = make_float4(s4[0], s4[1], s4[2], s4[3]);
            }
        }
        __syncthreads();   // samp ready

        // ---- MMA: warp tile 32 pix x 32 o, 2-pass tf32 split (a exact, b rounded)
        {
            const uint2* bsrc = (const uint2*)g_bf;
            uint2 bcur[4], bnxt[4];
            #pragma unroll
            for (int j = 0; j < 4; j++)
                bcur[j] = __ldg(bsrc + ((k*8 + 0)*8 + og*4 + j)*32 + lane);

            const int prow = pg*32 + (lane >> 2);
            #pragma unroll
            for (int q = 0; q < 8; q++) {
                if (q < 7) {
                    #pragma unroll
                    for (int j = 0; j < 4; j++)
                        bnxt[j] = __ldg(bsrc + ((k*8 + q+1)*8 + og*4 + j)*32 + lane);
                }
                const int ccol = q*8 + (lane & 3);
                uint32_t ah[2][4], al[2][4];
                #pragma unroll
                for (int tt = 0; tt < 2; tt++) {
                    const float* ps = smem + S_SAMP + (prow + 16*tt)*ST + ccol;
                    float a0 = ps[0];
                    float a1 = ps[8*ST];
                    float a2 = ps[4];
                    float a3 = ps[8*ST + 4];
                    float h0 = tf32r(a0), h1 = tf32r(a1), h2 = tf32r(a2), h3 = tf32r(a3);
                    ah[tt][0] = __float_as_uint(h0);
                    ah[tt][1] = __float_as_uint(h1);
                    ah[tt][2] = __float_as_uint(h2);
                    ah[tt][3] = __float_as_uint(h3);
                    al[tt][0] = __float_as_uint(a0 - h0);
                    al[tt][1] = __float_as_uint(a1 - h1);
                    al[tt][2] = __float_as_uint(a2 - h2);
                    al[tt][3] = __float_as_uint(a3 - h3);
                }
                #pragma unroll
                for (int j = 0; j < 4; j++) {
                    uint32_t b0 = bcur[j].x, b1 = bcur[j].y;
                    mma_tf32(acc[0][j], ah[0], b0, b1);
                    mma_tf32(acc[0][j], al[0], b0, b1);
                    mma_tf32(acc[1][j], ah[1], b0, b1);
                    mma_tf32(acc[1][j], al[1], b0, b1);
                }
                #pragma unroll
                for (int j = 0; j < 4; j++) bcur[j] = bnxt[j];
            }
        }
    }

    // ---- Epilogue: fragment regs -> out, add bias ----
    const int pix0 = pg*32 + (lane >> 2);
    const int o00  = og*32 + 2*(lane & 3);
    float* ob = out + (size_t)b*OO*HW + h*WW;
    #pragma unroll
    for (int t = 0; t < 2; t++) {
        int p = pix0 + 16*t;
        #pragma unroll
        for (int j = 0; j < 4; j++) {
            int o = o00 + 8*j;
            float b0 = smem[S_BIAS + o];
            float b1 = smem[S_BIAS + o + 1];
            ob[(size_t)o*HW + p]         = acc[t][j][0] + b0;
            ob[(size_t)(o+1)*HW + p]     = acc[t][j][1] + b1;
            ob[(size_t)o*HW + p + 8]     = acc[t][j][2] + b0;
            ob[(size_t)(o+1)*HW + p + 8] = acc[t][j][3] + b1;
        }
    }
}

extern "C" void kernel_launch(void* const* d_in, const int* in_sizes, int n_in,
                              void* d_out, int out_size) {
    const float* x        = (const float*)d_in[0];
    const float* off_w    = (const float*)d_in[1];
    const float* off_b    = (const float*)d_in[2];
    const float* bn_gamma = (const float*)d_in[3];
    const float* bn_beta  = (const float*)d_in[4];
    const float* bn_mean  = (const float*)d_in[5];
    const float* bn_var   = (const float*)d_in[6];
    const float* dconv_w  = (const float*)d_in[7];
    const float* dconv_b  = (const float*)d_in[8];
    float* out = (float*)d_out;

    cudaFuncSetAttribute(deform_main_kernel,
                         cudaFuncAttributeMaxDynamicSharedMemorySize, SMEM_BYTES);

    prep_bf_kernel<<<(KT*8*8*32 + 255)/256, 256>>>(dconv_w);
    deform_main_kernel<<<BB*HH, 256, SMEM_BYTES>>>(
        x, off_w, off_b, bn_gamma, bn_beta, bn_mean, bn_var, dconv_b, out);
}

// round 9
// speedup vs baseline: 2.2787x; 1.0709x over previous
#include <cuda_runtime.h>
#include <math.h>
#include <stdint.h>

#define BB 4
#define CC 64
#define OO 64
#define HH 128
#define WW 128
#define HW (HH*WW)
#define KT 9
#define ST 68    // samp row stride (floats): 68 mod 32 == 4 -> conflict-free

// ---- smem layout (float offsets) ----
#define S_SAMP0 0                 // samp fp32 [128][68]  (8704)
#define S_SAMP1 8704              // samp fp32 [128][68]  (8704)
#define S_OFFJ  17408             // [18][128]            (2304)
#define S_OFFW  19712             // [64][20]             (1280)
#define S_SC    20992             // [18]
#define S_SB    21010             // [18]
#define S_BIAS  21028             // [64]
#define SMEM_FLOATS 21092
#define SMEM_BYTES (SMEM_FLOATS*4)

// B fragments (hi only): [k][q][nt][lane][2] = (b0_hi, b1_hi)
__device__ float g_bf[KT*8*8*32*2];

__device__ __forceinline__ float tf32r(float a) {
    uint32_t u;
    asm("cvt.rna.tf32.f32 %0, %1;" : "=r"(u) : "f"(a));
    return __uint_as_float(u);
}

__global__ void prep_bf_kernel(const float* __restrict__ w) {
    int i = blockIdx.x * 256 + threadIdx.x;         // over KT*8*8*32 = 18432
    if (i >= KT*8*8*32) return;
    int lane = i & 31;
    int nt   = (i >> 5) & 7;
    int q    = (i >> 8) & 7;
    int k    = i >> 11;
    int cc  = lane & 3;
    int gid = lane >> 2;
    int o   = nt*8 + gid;
    int c0  = q*8 + cc;
    int c1  = c0 + 4;
    float w0 = w[(o*CC + c0)*KT + k];
    float w1 = w[(o*CC + c1)*KT + k];
    ((float2*)g_bf)[i] = make_float2(tf32r(w0), tf32r(w1));
}

__device__ __forceinline__ void mma_tf32(float* d, const uint32_t* a, uint32_t b0, uint32_t b1) {
    asm volatile(
        "mma.sync.aligned.m16n8k8.row.col.f32.tf32.tf32.f32 "
        "{%0,%1,%2,%3}, {%4,%5,%6,%7}, {%8,%9}, {%0,%1,%2,%3};"
        : "+f"(d[0]), "+f"(d[1]), "+f"(d[2]), "+f"(d[3])
        : "r"(a[0]), "r"(a[1]), "r"(a[2]), "r"(a[3]), "r"(b0), "r"(b1));
}

__global__ __launch_bounds__(256, 2) void deform_main_kernel(
    const float* __restrict__ x,
    const float* __restrict__ off_w,
    const float* __restrict__ off_b,
    const float* __restrict__ bn_gamma,
    const float* __restrict__ bn_beta,
    const float* __restrict__ bn_mean,
    const float* __restrict__ bn_var,
    const float* __restrict__ dconv_b,
    float* __restrict__ out)
{
    extern __shared__ float smem[];

    const int tid  = threadIdx.x;
    const int lane = tid & 31;
    const int wid  = tid >> 5;          // 8 warps
    const int b    = blockIdx.x >> 7;
    const int h    = blockIdx.x & 127;
    const int pix  = tid & 127;         // gather pixel (warp = 32 consecutive)
    const int half = tid >> 7;          // gathers channels [32*half, 32*half+32)
    const float* xb = x + (size_t)b * CC * HW;

    // ---- Prologue ----
    for (int i = tid; i < 18*CC; i += 256) {
        int j = i / CC, c = i % CC;
        smem[S_OFFW + c*20 + j] = off_w[i];
    }
    if (tid < 18) {
        float sc = bn_gamma[tid] * rsqrtf(bn_var[tid] + 1e-5f);
        smem[S_SC + tid] = sc;
        smem[S_SB + tid] = (off_b[tid] - bn_mean[tid]) * sc + bn_beta[tid];
    }
    if (tid >= 64 && tid < 128) smem[S_BIAS + tid - 64] = dconv_b[tid - 64];
    __syncthreads();

    // ---- Offset branch: 2 threads per pixel, 9 j's each ----
    {
        const int jb = half * 9;
        const int p  = h*WW + pix;
        float a9[9];
        #pragma unroll
        for (int j = 0; j < 9; j++) a9[j] = 0.f;
        #pragma unroll 4
        for (int c = 0; c < CC; c++) {
            float xv = __ldg(xb + c*HW + p);
            const float* r = smem + S_OFFW + c*20 + jb;
            #pragma unroll
            for (int j = 0; j < 9; j++) a9[j] += xv * r[j];
        }
        #pragma unroll
        for (int jj = 0; jj < 9; jj++) {
            int j = jb + jj;
            float v = a9[jj] * smem[S_SC + j] + smem[S_SB + j];
            smem[S_OFFJ + j*128 + pix] = tanhf(v) * 0.75f;
        }
    }
    __syncthreads();

    // corner computation for tap k at this thread's gather pixel
    auto corners = [&](int k, float4& wv, int4& iv) {
        const int kyi = k / 3 - 1;
        const int kxi = k % 3 - 1;
        float py = (float)(h + kyi)   + smem[S_OFFJ + (2*k)*128 + pix];
        float px = (float)(pix + kxi) + smem[S_OFFJ + (2*k+1)*128 + pix];
        float fy = floorf(py), fx = floorf(px);
        float wy = py - fy,    wx = px - fx;
        int y0 = (int)fy, x0 = (int)fx;
        int y1 = y0 + 1,  x1 = x0 + 1;
        float vy0 = (y0 >= 0 && y0 < HH) ? 1.f : 0.f;
        float vy1 = (y1 >= 0 && y1 < HH) ? 1.f : 0.f;
        float vx0 = (x0 >= 0 && x0 < WW) ? 1.f : 0.f;
        float vx1 = (x1 >= 0 && x1 < WW) ? 1.f : 0.f;
        wv.x = (1.f - wy) * (1.f - wx) * vy0 * vx0;
        wv.y = (1.f - wy) * wx         * vy0 * vx1;
        wv.z = wy         * (1.f - wx) * vy1 * vx0;
        wv.w = wy         * wx         * vy1 * vx1;
        int yc0 = min(max(y0, 0), HH-1), yc1 = min(max(y1, 0), HH-1);
        int xc0 = min(max(x0, 0), WW-1), xc1 = min(max(x1, 0), WW-1);
        iv.x = yc0*WW + xc0; iv.y = yc0*WW + xc1;
        iv.z = yc1*WW + xc0; iv.w = yc1*WW + xc1;
    };

    // MMA warp roles: pg = pixel group (32 pix), og = output group (32 o)
    const int pg = wid >> 1;
    const int og = wid & 1;
    const int cb = half * 32;          // gather channel base

    // ---- Pre-loop: gather tap 0 -> SAMP0 ----
    {
        float4 wv; int4 iv;
        corners(0, wv, iv);
        float* as = smem + S_SAMP0 + pix*ST + cb;
        #pragma unroll
        for (int g = 0; g < 8; g++) {
            float s4[4];
            #pragma unroll
            for (int e = 0; e < 4; e++) {
                const float* bp = xb + (size_t)(cb + g*4 + e)*HW;
                s4[e] = wv.x*__ldg(bp + iv.x) + wv.y*__ldg(bp + iv.y)
                      + wv.z*__ldg(bp + iv.z) + wv.w*__ldg(bp + iv.w);
            }
            *(float4*)(as + g*4) = make_float4(s4[0], s4[1], s4[2], s4[3]);
        }
    }
    __syncthreads();

    float acc[2][4][4];
    #pragma unroll
    for (int t = 0; t < 2; t++)
        #pragma unroll
        for (int n = 0; n < 4; n++)
            #pragma unroll
            for (int e = 0; e < 4; e++) acc[t][n][e] = 0.f;

    #pragma unroll 1
    for (int k = 0; k < KT; k++) {
        const float* s_cur = smem + ((k & 1) ? S_SAMP1 : S_SAMP0);
        float*       s_nxt = smem + ((k & 1) ? S_SAMP0 : S_SAMP1);
        const bool pf = (k < KT-1);

        float4 wv; int4 iv;
        if (pf) corners(k+1, wv, iv);

        const uint2* bsrc = (const uint2*)g_bf;
        uint2 bcur[4], bnxt[4];
        #pragma unroll
        for (int j = 0; j < 4; j++)
            bcur[j] = __ldg(bsrc + ((k*8 + 0)*8 + og*4 + j)*32 + lane);

        const int prow = pg*32 + (lane >> 2);
        float* as_n = s_nxt + pix*ST + cb;

        #pragma unroll
        for (int q = 0; q < 8; q++) {
            // issue gather LDGs for 4 channels of tap k+1 (latency hidden by MMAs)
            float v[16];
            if (pf) {
                #pragma unroll
                for (int e = 0; e < 4; e++) {
                    const float* bp = xb + (size_t)(cb + q*4 + e)*HW;
                    v[4*e+0] = __ldg(bp + iv.x);
                    v[4*e+1] = __ldg(bp + iv.y);
                    v[4*e+2] = __ldg(bp + iv.z);
                    v[4*e+3] = __ldg(bp + iv.w);
                }
            }
            if (q < 7) {
                #pragma unroll
                for (int j = 0; j < 4; j++)
                    bnxt[j] = __ldg(bsrc + ((k*8 + q+1)*8 + og*4 + j)*32 + lane);
            }

            // A fragments from current samp, hi/lo derived in registers
            const int ccol = q*8 + (lane & 3);
            uint32_t ah[2][4], al[2][4];
            #pragma unroll
            for (int tt = 0; tt < 2; tt++) {
                const float* ps = s_cur + (prow + 16*tt)*ST + ccol;
                float a0 = ps[0];
                float a1 = ps[8*ST];
                float a2 = ps[4];
                float a3 = ps[8*ST + 4];
                float h0 = tf32r(a0), h1 = tf32r(a1), h2 = tf32r(a2), h3 = tf32r(a3);
                ah[tt][0] = __float_as_uint(h0);
                ah[tt][1] = __float_as_uint(h1);
                ah[tt][2] = __float_as_uint(h2);
                ah[tt][3] = __float_as_uint(h3);
                al[tt][0] = __float_as_uint(a0 - h0);
                al[tt][1] = __float_as_uint(a1 - h1);
                al[tt][2] = __float_as_uint(a2 - h2);
                al[tt][3] = __float_as_uint(a3 - h3);
            }
            #pragma unroll
            for (int j = 0; j < 4; j++) {
                uint32_t b0 = bcur[j].x, b1 = bcur[j].y;
                mma_tf32(acc[0][j], ah[0], b0, b1);
                mma_tf32(acc[0][j], al[0], b0, b1);
                mma_tf32(acc[1][j], ah[1], b0, b1);
                mma_tf32(acc[1][j], al[1], b0, b1);
            }
            #pragma unroll
            for (int j = 0; j < 4; j++) bcur[j] = bnxt[j];

            // combine gathered corners and store to next samp buffer
            if (pf) {
                float s0 = wv.x*v[0]  + wv.y*v[1]  + wv.z*v[2]  + wv.w*v[3];
                float s1 = wv.x*v[4]  + wv.y*v[5]  + wv.z*v[6]  + wv.w*v[7];
                float s2 = wv.x*v[8]  + wv.y*v[9]  + wv.z*v[10] + wv.w*v[11];
                float s3 = wv.x*v[12] + wv.y*v[13] + wv.z*v[14] + wv.w*v[15];
                *(float4*)(as_n + q*4) = make_float4(s0, s1, s2, s3);
            }
        }

        __syncthreads();   // samp_nxt complete; all reads of samp_cur done
    }

    // ---- Epilogue: fragment regs -> out, add bias ----
    const int pix0 = pg*32 + (lane >> 2);
    const int o00  = og*32 + 2*(lane & 3);
    float* ob = out + (size_t)b*OO*HW + h*WW;
    #pragma unroll
    for (int t = 0; t < 2; t++) {
        int p = pix0 + 16*t;
        #pragma unroll
        for (int j = 0; j < 4; j++) {
            int o = o00 + 8*j;
            float b0 = smem[S_BIAS + o];
            float b1 = smem[S_BIAS + o + 1];
            ob[(size_t)o*HW + p]         = acc[t][j][0] + b0;
            ob[(size_t)(o+1)*HW + p]     = acc[t][j][1] + b1;
            ob[(size_t)o*HW + p + 8]     = acc[t][j][2] + b0;
            ob[(size_t)(o+1)*HW + p + 8] = acc[t][j][3] + b1;
        }
    }
}

extern "C" void kernel_launch(void* const* d_in, const int* in_sizes, int n_in,
                              void* d_out, int out_size) {
    const float* x        = (const float*)d_in[0];
    const float* off_w    = (const float*)d_in[1];
    const float* off_b    = (const float*)d_in[2];
    const float* bn_gamma = (const float*)d_in[3];
    const float* bn_beta  = (const float*)d_in[4];
    const float* bn_mean  = (const float*)d_in[5];
    const float* bn_var   = (const float*)d_in[6];
    const float* dconv_w  = (const float*)d_in[7];
    const float* dconv_b  = (const float*)d_in[8];
    float* out = (float*)d_out;

    cudaFuncSetAttribute(deform_main_kernel,
                         cudaFuncAttributeMaxDynamicSharedMemorySize, SMEM_BYTES);

    prep_bf_kernel<<<(KT*8*8*32 + 255)/256, 256>>>(dconv_w);
    deform_main_kernel<<<BB*HH, 256, SMEM_BYTES>>>(
        x, off_w, off_b, bn_gamma, bn_beta, bn_mean, bn_var, dconv_b, out);
}

// round 10
// speedup vs baseline: 2.6231x; 1.1511x over previous
#include <cuda_runtime.h>
#include <math.h>
#include <stdint.h>

#define BB 4
#define CC 64
#define OO 64
#define HH 128
#define WW 128
#define HW (HH*WW)
#define KT 9
#define PX 64    // pixels per block (half row)
#define ST 68    // samp row stride (floats): 68 mod 32 == 4 -> conflict-free

// ---- smem layout (float offsets) ----
#define S_SAMP0 0                 // samp fp32 [64][68]   (4352)
#define S_SAMP1 4352              // samp fp32 [64][68]   (4352)
#define S_OFFJ  8704              // [18][64]             (1152)
#define S_OFFW  9856              // [64][20]             (1280)
#define S_SC    11136             // [18]
#define S_SB    11154             // [18]
#define S_BIAS  11172             // [64]
#define SMEM_FLOATS 11236
#define SMEM_BYTES (SMEM_FLOATS*4)

// B fragments (hi only): [k][q][nt][lane][2] = (b0_hi, b1_hi)
__device__ float g_bf[KT*8*8*32*2];

__device__ __forceinline__ float tf32r(float a) {
    uint32_t u;
    asm("cvt.rna.tf32.f32 %0, %1;" : "=r"(u) : "f"(a));
    return __uint_as_float(u);
}

__global__ void prep_bf_kernel(const float* __restrict__ w) {
    int i = blockIdx.x * 256 + threadIdx.x;         // over KT*8*8*32 = 18432
    if (i >= KT*8*8*32) return;
    int lane = i & 31;
    int nt   = (i >> 5) & 7;
    int q    = (i >> 8) & 7;
    int k    = i >> 11;
    int cc  = lane & 3;
    int gid = lane >> 2;
    int o   = nt*8 + gid;
    int c0  = q*8 + cc;
    int c1  = c0 + 4;
    float w0 = w[(o*CC + c0)*KT + k];
    float w1 = w[(o*CC + c1)*KT + k];
    ((float2*)g_bf)[i] = make_float2(tf32r(w0), tf32r(w1));
}

__device__ __forceinline__ void mma_tf32(float* d, const uint32_t* a, uint32_t b0, uint32_t b1) {
    asm volatile(
        "mma.sync.aligned.m16n8k8.row.col.f32.tf32.tf32.f32 "
        "{%0,%1,%2,%3}, {%4,%5,%6,%7}, {%8,%9}, {%0,%1,%2,%3};"
        : "+f"(d[0]), "+f"(d[1]), "+f"(d[2]), "+f"(d[3])
        : "r"(a[0]), "r"(a[1]), "r"(a[2]), "r"(a[3]), "r"(b0), "r"(b1));
}

__global__ __launch_bounds__(128, 4) void deform_main_kernel(
    const float* __restrict__ x,
    const float* __restrict__ off_w,
    const float* __restrict__ off_b,
    const float* __restrict__ bn_gamma,
    const float* __restrict__ bn_beta,
    const float* __restrict__ bn_mean,
    const float* __restrict__ bn_var,
    const float* __restrict__ dconv_b,
    float* __restrict__ out)
{
    extern __shared__ float smem[];

    const int tid  = threadIdx.x;
    const int lane = tid & 31;
    const int wid  = tid >> 5;          // 4 warps
    const int blk  = blockIdx.x;        // 1024 = BB*HH*2
    const int b    = blk >> 8;
    const int h    = (blk >> 1) & 127;
    const int w0   = (blk & 1) * PX;    // half-row pixel base
    const int pix  = tid & 63;          // gather pixel within half row
    const int half = tid >> 6;          // gathers channels [32*half, 32*half+32)
    const float* xb = x + (size_t)b * CC * HW;

    // ---- Prologue ----
    for (int i = tid; i < 18*CC; i += 128) {
        int j = i / CC, c = i % CC;
        smem[S_OFFW + c*20 + j] = off_w[i];
    }
    if (tid < 18) {
        float sc = bn_gamma[tid] * rsqrtf(bn_var[tid] + 1e-5f);
        smem[S_SC + tid] = sc;
        smem[S_SB + tid] = (off_b[tid] - bn_mean[tid]) * sc + bn_beta[tid];
    }
    if (tid >= 64 && tid < 128) smem[S_BIAS + tid - 64] = dconv_b[tid - 64];
    __syncthreads();

    // ---- Offset branch: 2 threads per pixel, 9 j's each ----
    {
        const int jb = half * 9;
        const int p  = h*WW + w0 + pix;
        float a9[9];
        #pragma unroll
        for (int j = 0; j < 9; j++) a9[j] = 0.f;
        #pragma unroll 4
        for (int c = 0; c < CC; c++) {
            float xv = __ldg(xb + c*HW + p);
            const float* r = smem + S_OFFW + c*20 + jb;
            #pragma unroll
            for (int j = 0; j < 9; j++) a9[j] += xv * r[j];
        }
        #pragma unroll
        for (int jj = 0; jj < 9; jj++) {
            int j = jb + jj;
            float v = a9[jj] * smem[S_SC + j] + smem[S_SB + j];
            smem[S_OFFJ + j*PX + pix] = tanhf(v) * 0.75f;
        }
    }
    __syncthreads();

    const int cb = half * 32;                         // gather channel base
    const char* xcb = (const char*)(xb + (size_t)cb * HW);

    // corner computation: returns bilinear weights + 4 byte-base pointers
    auto corners = [&](int k, float4& wv, const char*& p0, const char*& p1,
                       const char*& p2, const char*& p3) {
        const int kyi = k / 3 - 1;
        const int kxi = k % 3 - 1;
        float py = (float)(h + kyi)        + smem[S_OFFJ + (2*k)*PX + pix];
        float px = (float)(w0 + pix + kxi) + smem[S_OFFJ + (2*k+1)*PX + pix];
        float fy = floorf(py), fx = floorf(px);
        float wy = py - fy,    wx = px - fx;
        int y0 = (int)fy, x0 = (int)fx;
        int y1 = y0 + 1,  x1 = x0 + 1;
        float vy0 = (y0 >= 0 && y0 < HH) ? 1.f : 0.f;
        float vy1 = (y1 >= 0 && y1 < HH) ? 1.f : 0.f;
        float vx0 = (x0 >= 0 && x0 < WW) ? 1.f : 0.f;
        float vx1 = (x1 >= 0 && x1 < WW) ? 1.f : 0.f;
        wv.x = (1.f - wy) * (1.f - wx) * vy0 * vx0;
        wv.y = (1.f - wy) * wx         * vy0 * vx1;
        wv.z = wy         * (1.f - wx) * vy1 * vx0;
        wv.w = wy         * wx         * vy1 * vx1;
        int yc0 = min(max(y0, 0), HH-1), yc1 = min(max(y1, 0), HH-1);
        int xc0 = min(max(x0, 0), WW-1), xc1 = min(max(x1, 0), WW-1);
        p0 = xcb + 4u*(uint32_t)(yc0*WW + xc0);
        p1 = xcb + 4u*(uint32_t)(yc0*WW + xc1);
        p2 = xcb + 4u*(uint32_t)(yc1*WW + xc0);
        p3 = xcb + 4u*(uint32_t)(yc1*WW + xc1);
    };

    // MMA warp roles: pg = pixel group (32 pix), og = output group (32 o)
    const int pg = wid >> 1;
    const int og = wid & 1;

    // ---- Pre-loop: gather tap 0 -> SAMP0 ----
    {
        float4 wv; const char *p0, *p1, *p2, *p3;
        corners(0, wv, p0, p1, p2, p3);
        float* as = smem + S_SAMP0 + pix*ST + cb;
        #pragma unroll
        for (int g = 0; g < 8; g++) {
            float s4[4];
            #pragma unroll
            for (int e = 0; e < 4; e++) {
                const int co = (g*4 + e) * (HW*4);    // compile-time imm per unroll
                s4[e] = wv.x*__ldg((const float*)(p0 + co))
                      + wv.y*__ldg((const float*)(p1 + co))
                      + wv.z*__ldg((const float*)(p2 + co))
                      + wv.w*__ldg((const float*)(p3 + co));
            }
            *(float4*)(as + g*4) = make_float4(s4[0], s4[1], s4[2], s4[3]);
        }
    }
    __syncthreads();

    float acc[2][4][4];
    #pragma unroll
    for (int t = 0; t < 2; t++)
        #pragma unroll
        for (int n = 0; n < 4; n++)
            #pragma unroll
            for (int e = 0; e < 4; e++) acc[t][n][e] = 0.f;

    #pragma unroll 1
    for (int k = 0; k < KT; k++) {
        const float* s_cur = smem + ((k & 1) ? S_SAMP1 : S_SAMP0);
        float*       s_nxt = smem + ((k & 1) ? S_SAMP0 : S_SAMP1);
        const bool pf = (k < KT-1);

        float4 wv; const char *p0, *p1, *p2, *p3;
        if (pf) corners(k+1, wv, p0, p1, p2, p3);

        const char* bq = (const char*)g_bf + ((size_t)(k*8)*8 + og*4)*256 + lane*8;
        uint2 bcur[4], bnxt[4];
        #pragma unroll
        for (int j = 0; j < 4; j++)
            bcur[j] = __ldg((const uint2*)(bq + j*256));
        bq += 2048;

        const int prow = pg*32 + (lane >> 2);
        float* as_n = s_nxt + pix*ST + cb;

        #pragma unroll
        for (int q = 0; q < 8; q++) {
            // issue gather LDGs for 4 channels of tap k+1 (latency hidden by MMAs)
            float v[16];
            if (pf) {
                #pragma unroll
                for (int e = 0; e < 4; e++) {
                    const int co = (q*4 + e) * (HW*4);
                    v[4*e+0] = __ldg((const float*)(p0 + co));
                    v[4*e+1] = __ldg((const float*)(p1 + co));
                    v[4*e+2] = __ldg((const float*)(p2 + co));
                    v[4*e+3] = __ldg((const float*)(p3 + co));
                }
            }
            if (q < 7) {
                #pragma unroll
                for (int j = 0; j < 4; j++)
                    bnxt[j] = __ldg((const uint2*)(bq + j*256));
                bq += 2048;
            }

            // A fragments from current samp, hi/lo derived in registers
            const int ccol = q*8 + (lane & 3);
            uint32_t ah[2][4], al[2][4];
            #pragma unroll
            for (int tt = 0; tt < 2; tt++) {
                const float* ps = s_cur + (prow + 16*tt)*ST + ccol;
                float a0 = ps[0];
                float a1 = ps[8*ST];
                float a2 = ps[4];
                float a3 = ps[8*ST + 4];
                float h0 = tf32r(a0), h1 = tf32r(a1), h2 = tf32r(a2), h3 = tf32r(a3);
                ah[tt][0] = __float_as_uint(h0);
                ah[tt][1] = __float_as_uint(h1);
                ah[tt][2] = __float_as_uint(h2);
                ah[tt][3] = __float_as_uint(h3);
                al[tt][0] = __float_as_uint(a0 - h0);
                al[tt][1] = __float_as_uint(a1 - h1);
                al[tt][2] = __float_as_uint(a2 - h2);
                al[tt][3] = __float_as_uint(a3 - h3);
            }
            #pragma unroll
            for (int j = 0; j < 4; j++) {
                uint32_t b0 = bcur[j].x, b1 = bcur[j].y;
                mma_tf32(acc[0][j], ah[0], b0, b1);
                mma_tf32(acc[0][j], al[0], b0, b1);
                mma_tf32(acc[1][j], ah[1], b0, b1);
                mma_tf32(acc[1][j], al[1], b0, b1);
            }
            #pragma unroll
            for (int j = 0; j < 4; j++) bcur[j] = bnxt[j];

            // combine gathered corners and store to next samp buffer
            if (pf) {
                float s0 = wv.x*v[0]  + wv.y*v[1]  + wv.z*v[2]  + wv.w*v[3];
                float s1 = wv.x*v[4]  + wv.y*v[5]  + wv.z*v[6]  + wv.w*v[7];
                float s2 = wv.x*v[8]  + wv.y*v[9]  + wv.z*v[10] + wv.w*v[11];
                float s3 = wv.x*v[12] + wv.y*v[13] + wv.z*v[14] + wv.w*v[15];
                *(float4*)(as_n + q*4) = make_float4(s0, s1, s2, s3);
            }
        }

        __syncthreads();   // samp_nxt complete; all reads of samp_cur done
    }

    // ---- Epilogue: fragment regs -> out, add bias ----
    const int pix0 = pg*32 + (lane >> 2);
    const int o00  = og*32 + 2*(lane & 3);
    float* ob = out + (size_t)b*OO*HW + h*WW + w0;
    #pragma unroll
    for (int t = 0; t < 2; t++) {
        int p = pix0 + 16*t;
        #pragma unroll
        for (int j = 0; j < 4; j++) {
            int o = o00 + 8*j;
            float b0 = smem[S_BIAS + o];
            float b1 = smem[S_BIAS + o + 1];
            ob[(size_t)o*HW + p]         = acc[t][j][0] + b0;
            ob[(size_t)(o+1)*HW + p]     = acc[t][j][1] + b1;
            ob[(size_t)o*HW + p + 8]     = acc[t][j][2] + b0;
            ob[(size_t)(o+1)*HW + p + 8] = acc[t][j][3] + b1;
        }
    }
}

extern "C" void kernel_launch(void* const* d_in, const int* in_sizes, int n_in,
                              void* d_out, int out_size) {
    const float* x        = (const float*)d_in[0];
    const float* off_w    = (const float*)d_in[1];
    const float* off_b    = (const float*)d_in[2];
    const float* bn_gamma = (const float*)d_in[3];
    const float* bn_beta  = (const float*)d_in[4];
    const float* bn_mean  = (const float*)d_in[5];
    const float* bn_var   = (const float*)d_in[6];
    const float* dconv_w  = (const float*)d_in[7];
    const float* dconv_b  = (const float*)d_in[8];
    float* out = (float*)d_out;

    cudaFuncSetAttribute(deform_main_kernel,
                         cudaFuncAttributeMaxDynamicSharedMemorySize, SMEM_BYTES);

    prep_bf_kernel<<<(KT*8*8*32 + 255)/256, 256>>>(dconv_w);
    deform_main_kernel<<<BB*HH*2, 128, SMEM_BYTES>>>(
        x, off_w, off_b, bn_gamma, bn_beta, bn_mean, bn_var, dconv_b, out);
}